// round 13
// baseline (speedup 1.0000x reference)
#include <cuda_runtime.h>
#include <math.h>

// Quaternion LSTM: T=128, B=64, F=512, H=1024.
// Round 13: R12 base (best, 4975us) + sync overhaul:
//   1) atomic-free grid barrier: per-CTA generation-tagged flags (128B stride),
//      CTA0 polls, publishes g_gen. No same-address atomic serialization.
//   2) update phase spread across ALL 256 CTAs (64 quads each)
//   3) launch order: recurrence is 4th kernel -> ncu captures it
// GEMM math bit-identical to R12 (rel_err must stay 6.588118e-07).

#define T_ 128
#define B_ 64
#define Fdim 512
#define H_ 1024
#define N4 (4 * H_)          // 4096
#define FO (Fdim + 1)        // 513
#define SPLITK 8
#define KCHUNK (H_ / SPLITK) // 128
#define NCTA 256

// ---- scratch (static device globals: allocation-free) ----
__device__ float g_Wcat[(size_t)Fdim * N4];            //  8 MB
__device__ float g_bias4[N4];
__device__ float g_Ucat[(size_t)H_ * N4];              // 16 MB
__device__ float g_G[(size_t)T_ * B_ * N4];            // 128 MB (pre-gates)
__device__ float g_preK[(size_t)SPLITK * B_ * N4];     //  8 MB
__device__ float g_h[B_ * H_];
__device__ float g_c[B_ * H_];
__device__ float g_Hbuf[(size_t)T_ * B_ * H_];         // 32 MB
__device__ unsigned g_flags[NCTA * 32];                // 32 KB, 128B stride
__device__ volatile unsigned g_gen;

__device__ const float c_sgn[16] = {
    1.f, -1.f, -1.f, -1.f,
    1.f,  1.f, -1.f,  1.f,
    1.f,  1.f,  1.f, -1.f,
    1.f, -1.f,  1.f,  1.f
};

// ---------------- builds ----------------
__global__ void build_W(const float* __restrict__ wf, const float* __restrict__ wi,
                        const float* __restrict__ wo, const float* __restrict__ wc) {
    int idx = blockIdx.x * blockDim.x + threadIdx.x;
    if (idx >= Fdim * N4) return;
    int row  = idx / N4;
    int col  = idx % N4;
    int gate = col / H_;
    int cj   = col % H_;
    int rb = row / (Fdim / 4), a = row % (Fdim / 4);
    int cb = cj / (H_ / 4),    b = cj % (H_ / 4);
    const float* w = (gate == 0) ? wf : (gate == 1) ? wi : (gate == 2) ? wo : wc;
    g_Wcat[idx] = c_sgn[cb * 4 + rb] *
                  w[((size_t)(rb ^ cb) * (Fdim / 4) + a) * (H_ / 4) + b];
}

// build_U + all state/bias/barrier init (keeps recurrence at launch slot 4)
__global__ void build_U_init(const float* __restrict__ uf, const float* __restrict__ ui,
                             const float* __restrict__ uo, const float* __restrict__ uc,
                             const float* __restrict__ bf, const float* __restrict__ bi,
                             const float* __restrict__ bo, const float* __restrict__ bc) {
    int idx = blockIdx.x * blockDim.x + threadIdx.x;
    if (idx < B_ * H_) { g_h[idx] = 0.f; g_c[idx] = 0.f; }
    if (idx < NCTA * 32) g_flags[idx] = 0;
    if (idx == 0) g_gen = 0;
    if (idx < N4) {
        int gate = idx / H_, j = idx % H_;
        const float* b = (gate == 0) ? bf : (gate == 1) ? bi : (gate == 2) ? bo : bc;
        g_bias4[idx] = b[j];
    }
    if (idx >= H_ * N4) return;
    int row  = idx / N4;
    int col  = idx % N4;
    int gate = col / H_;
    int cj   = col % H_;
    int rb = row / (H_ / 4), a = row % (H_ / 4);
    int cb = cj / (H_ / 4),  b = cj % (H_ / 4);
    const float* w = (gate == 0) ? uf : (gate == 1) ? ui : (gate == 2) ? uo : uc;
    g_Ucat[idx] = c_sgn[cb * 4 + rb] *
                  w[((size_t)(rb ^ cb) * (H_ / 4) + a) * (H_ / 4) + b];
}

// ---------------- generic fp32 GEMM, double-buffered (R12-proven) ----------------
__device__ __forceinline__ void gemm_body(const float* __restrict__ A,
                                          const float* __restrict__ Bm,
                                          const float* __restrict__ bias,
                                          float* __restrict__ C,
                                          int M, int N, int K) {
    const int BM = 128, BN = 128, BK = 16;
    __shared__ __align__(16) float As[2][BK][BM];
    __shared__ __align__(16) float Bs[2][BK][BN];
    int tid = threadIdx.x;
    int tx = tid % 16, ty = tid / 16;
    int rowBase = blockIdx.y * BM;
    int colBase = blockIdx.x * BN;
    bool fullN = ((N & 3) == 0) && (colBase + BN <= N);
    float acc[8][8];
    #pragma unroll
    for (int i = 0; i < 8; i++)
        #pragma unroll
        for (int j = 0; j < 8; j++) acc[i][j] = 0.f;

    {   // preload chunk 0
        #pragma unroll
        for (int i = 0; i < 2; i++) {
            int lin = tid + i * 256;
            int r = lin >> 2, c4 = (lin & 3) * 4;
            float4 v = *reinterpret_cast<const float4*>(
                &A[(size_t)(rowBase + r) * K + c4]);
            As[0][c4 + 0][r] = v.x;
            As[0][c4 + 1][r] = v.y;
            As[0][c4 + 2][r] = v.z;
            As[0][c4 + 3][r] = v.w;
        }
        if (fullN) {
            #pragma unroll
            for (int i = 0; i < 2; i++) {
                int lin = tid + i * 256;
                int kk = lin >> 5, c4 = (lin & 31) * 4;
                float4 v = *reinterpret_cast<const float4*>(
                    &Bm[(size_t)kk * N + colBase + c4]);
                *reinterpret_cast<float4*>(&Bs[0][kk][c4]) = v;
            }
        } else {
            #pragma unroll
            for (int i = 0; i < 8; i++) {
                int lin = tid + i * 256;
                int kk = lin >> 7, n = lin & 127;
                int gn = colBase + n;
                Bs[0][kk][n] = (gn < N) ? Bm[(size_t)kk * N + gn] : 0.f;
            }
        }
    }
    __syncthreads();

    int buf = 0;
    for (int k0 = 0; k0 < K; k0 += BK) {
        bool more = (k0 + BK) < K;
        float4 pa[2];
        float4 pbv[2];
        float pbs[8];
        if (more) {
            int kn = k0 + BK;
            #pragma unroll
            for (int i = 0; i < 2; i++) {
                int lin = tid + i * 256;
                int r = lin >> 2, c4 = (lin & 3) * 4;
                pa[i] = *reinterpret_cast<const float4*>(
                    &A[(size_t)(rowBase + r) * K + kn + c4]);
            }
            if (fullN) {
                #pragma unroll
                for (int i = 0; i < 2; i++) {
                    int lin = tid + i * 256;
                    int kk = lin >> 5, c4 = (lin & 31) * 4;
                    pbv[i] = *reinterpret_cast<const float4*>(
                        &Bm[(size_t)(kn + kk) * N + colBase + c4]);
                }
            } else {
                #pragma unroll
                for (int i = 0; i < 8; i++) {
                    int lin = tid + i * 256;
                    int kk = lin >> 7, n = lin & 127;
                    int gn = colBase + n;
                    pbs[i] = (gn < N) ? Bm[(size_t)(kn + kk) * N + gn] : 0.f;
                }
            }
        }
        #pragma unroll
        for (int kk = 0; kk < BK; kk++) {
            float a[8], b[8];
            float4 a0 = *reinterpret_cast<const float4*>(&As[buf][kk][ty * 8]);
            float4 a1 = *reinterpret_cast<const float4*>(&As[buf][kk][ty * 8 + 4]);
            float4 b0 = *reinterpret_cast<const float4*>(&Bs[buf][kk][tx * 8]);
            float4 b1 = *reinterpret_cast<const float4*>(&Bs[buf][kk][tx * 8 + 4]);
            a[0]=a0.x; a[1]=a0.y; a[2]=a0.z; a[3]=a0.w;
            a[4]=a1.x; a[5]=a1.y; a[6]=a1.z; a[7]=a1.w;
            b[0]=b0.x; b[1]=b0.y; b[2]=b0.z; b[3]=b0.w;
            b[4]=b1.x; b[5]=b1.y; b[6]=b1.z; b[7]=b1.w;
            #pragma unroll
            for (int i = 0; i < 8; i++)
                #pragma unroll
                for (int j = 0; j < 8; j++)
                    acc[i][j] += a[i] * b[j];
        }
        if (more) {
            int nb = buf ^ 1;
            #pragma unroll
            for (int i = 0; i < 2; i++) {
                int lin = tid + i * 256;
                int r = lin >> 2, c4 = (lin & 3) * 4;
                As[nb][c4 + 0][r] = pa[i].x;
                As[nb][c4 + 1][r] = pa[i].y;
                As[nb][c4 + 2][r] = pa[i].z;
                As[nb][c4 + 3][r] = pa[i].w;
            }
            if (fullN) {
                #pragma unroll
                for (int i = 0; i < 2; i++) {
                    int lin = tid + i * 256;
                    int kk = lin >> 5, c4 = (lin & 31) * 4;
                    *reinterpret_cast<float4*>(&Bs[nb][kk][c4]) = pbv[i];
                }
            } else {
                #pragma unroll
                for (int i = 0; i < 8; i++) {
                    int lin = tid + i * 256;
                    int kk = lin >> 7, n = lin & 127;
                    Bs[nb][kk][n] = pbs[i];
                }
            }
        }
        __syncthreads();
        buf ^= 1;
    }
    #pragma unroll
    for (int i = 0; i < 8; i++) {
        int gm = rowBase + ty * 8 + i;
        if (gm >= M) continue;
        #pragma unroll
        for (int j = 0; j < 8; j++) {
            int gn = colBase + tx * 8 + j;
            if (gn >= N) continue;
            float v = acc[i][j];
            if (bias) v += bias[gn];
            C[(size_t)gm * N + gn] = v;
        }
    }
}

__global__ __launch_bounds__(256) void gemm_in(const float* __restrict__ x) {
    gemm_body(x, g_Wcat, g_bias4, g_G, T_ * B_, N4, Fdim);
}

__global__ __launch_bounds__(256) void gemm_out(const float* __restrict__ fw,
                                                const float* __restrict__ fb,
                                                float* __restrict__ out) {
    gemm_body(g_Hbuf, fw, fb, out, T_ * B_, FO, H_);
}

// ---------------- atomic-free grid barrier (generation-tagged flags) ----------
__device__ __forceinline__ void grid_barrier(unsigned k) {
    __syncthreads();
    __threadfence();   // release: this CTA's global writes visible device-wide
    if (threadIdx.x == 0)
        *(volatile unsigned*)&g_flags[blockIdx.x * 32] = k;
    if (blockIdx.x == 0) {
        volatile unsigned* f = (volatile unsigned*)&g_flags[threadIdx.x * 32];
        while (*f < k) { }
        __syncthreads();
        if (threadIdx.x == 0) { __threadfence(); g_gen = k; }
    }
    if (threadIdx.x == 0) {
        while (g_gen < k) { }
    }
    __syncthreads();
    __threadfence();   // acquire
}

// ---------------- persistent recurrence ----------------
__global__ __launch_bounds__(256, 2) void recurrence() {
    __shared__ __align__(16) float As[2][16][68];
    __shared__ __align__(16) float Bs[2][16][132];
    int tid = threadIdx.x;
    int tx = tid & 15, ty = tid >> 4;
    int nTile = blockIdx.x & 31;
    int s = blockIdx.x >> 5;
    int colBase = nTile * 128;
    int kbase = s * KCHUNK;
    // update phase: spread across all 256 CTAs, 64 quads each
    int q = blockIdx.x * 64 + (tid & 63);
    bool upd = tid < 64;
    float* preOut = g_preK + (size_t)s * B_ * N4;
    int ar = tid >> 2, ac4 = (tid & 3) * 4;

    for (int t = 0; t < T_; t++) {
        // ======== phase 1: pre = h @ Ucat (64 x 128 tile, K chunk s)
        float acc[4][8];
        #pragma unroll
        for (int i = 0; i < 4; i++)
            #pragma unroll
            for (int j = 0; j < 8; j++) acc[i][j] = 0.f;

        {   // preload chunk 0 into buffer 0
            float4 v = *reinterpret_cast<const float4*>(
                &g_h[(size_t)ar * H_ + kbase + ac4]);
            As[0][ac4 + 0][ar] = v.x;
            As[0][ac4 + 1][ar] = v.y;
            As[0][ac4 + 2][ar] = v.z;
            As[0][ac4 + 3][ar] = v.w;
            #pragma unroll
            for (int i = 0; i < 2; i++) {
                int lin = tid + i * 256;
                int kk = lin >> 5, c4 = (lin & 31) * 4;
                float4 bv = *reinterpret_cast<const float4*>(
                    &g_Ucat[(size_t)(kbase + kk) * N4 + colBase + c4]);
                *reinterpret_cast<float4*>(&Bs[0][kk][c4]) = bv;
            }
        }
        __syncthreads();

        int buf = 0;
        for (int k0 = 0; k0 < KCHUNK; k0 += 16) {
            bool more = (k0 + 16) < KCHUNK;
            float4 pa;
            float4 pb[2];
            if (more) {
                int kn = kbase + k0 + 16;
                pa = *reinterpret_cast<const float4*>(
                    &g_h[(size_t)ar * H_ + kn + ac4]);
                #pragma unroll
                for (int i = 0; i < 2; i++) {
                    int lin = tid + i * 256;
                    int kk = lin >> 5, c4 = (lin & 31) * 4;
                    pb[i] = *reinterpret_cast<const float4*>(
                        &g_Ucat[(size_t)(kn + kk) * N4 + colBase + c4]);
                }
            }
            #pragma unroll
            for (int kk = 0; kk < 16; kk++) {
                float4 av = *reinterpret_cast<const float4*>(&As[buf][kk][ty * 4]);
                float4 b0 = *reinterpret_cast<const float4*>(&Bs[buf][kk][tx * 8]);
                float4 b1 = *reinterpret_cast<const float4*>(&Bs[buf][kk][tx * 8 + 4]);
                float a[4] = {av.x, av.y, av.z, av.w};
                float b[8] = {b0.x, b0.y, b0.z, b0.w, b1.x, b1.y, b1.z, b1.w};
                #pragma unroll
                for (int i = 0; i < 4; i++)
                    #pragma unroll
                    for (int j = 0; j < 8; j++)
                        acc[i][j] += a[i] * b[j];
            }
            if (more) {
                int nb = buf ^ 1;
                As[nb][ac4 + 0][ar] = pa.x;
                As[nb][ac4 + 1][ar] = pa.y;
                As[nb][ac4 + 2][ar] = pa.z;
                As[nb][ac4 + 3][ar] = pa.w;
                #pragma unroll
                for (int i = 0; i < 2; i++) {
                    int lin = tid + i * 256;
                    int kk = lin >> 5, c4 = (lin & 31) * 4;
                    *reinterpret_cast<float4*>(&Bs[nb][kk][c4]) = pb[i];
                }
            }
            __syncthreads();
            buf ^= 1;
        }
        #pragma unroll
        for (int i = 0; i < 4; i++) {
            int r = ty * 4 + i;
            float4 v0 = {acc[i][0], acc[i][1], acc[i][2], acc[i][3]};
            float4 v1 = {acc[i][4], acc[i][5], acc[i][6], acc[i][7]};
            *reinterpret_cast<float4*>(&preOut[(size_t)r * N4 + colBase + tx * 8])     = v0;
            *reinterpret_cast<float4*>(&preOut[(size_t)r * N4 + colBase + tx * 8 + 4]) = v1;
        }

        grid_barrier(2 * t + 1);

        // ======== phase 2: gates + state update (64 quads per CTA, all SMs)
        if (upd) {
            int b = q >> 8;                 // q / 256
            int j = (q & 255) * 4;
            const float* Gt = g_G + (size_t)((size_t)t * B_ + b) * N4;
            float4 pf = *reinterpret_cast<const float4*>(&Gt[0 * H_ + j]);
            float4 pi = *reinterpret_cast<const float4*>(&Gt[1 * H_ + j]);
            float4 po = *reinterpret_cast<const float4*>(&Gt[2 * H_ + j]);
            float4 pa = *reinterpret_cast<const float4*>(&Gt[3 * H_ + j]);
            #pragma unroll
            for (int sp = 0; sp < SPLITK; sp++) {
                const float* pk = g_preK + (size_t)sp * B_ * N4 + (size_t)b * N4;
                float4 vf = *reinterpret_cast<const float4*>(&pk[0 * H_ + j]);
                float4 vi = *reinterpret_cast<const float4*>(&pk[1 * H_ + j]);
                float4 vo = *reinterpret_cast<const float4*>(&pk[2 * H_ + j]);
                float4 va = *reinterpret_cast<const float4*>(&pk[3 * H_ + j]);
                pf.x += vf.x; pf.y += vf.y; pf.z += vf.z; pf.w += vf.w;
                pi.x += vi.x; pi.y += vi.y; pi.z += vi.z; pi.w += vi.w;
                po.x += vo.x; po.y += vo.y; po.z += vo.z; po.w += vo.w;
                pa.x += va.x; pa.y += va.y; pa.z += va.z; pa.w += va.w;
            }
            float fv[4] = {pf.x, pf.y, pf.z, pf.w};
            float iv[4] = {pi.x, pi.y, pi.z, pi.w};
            float ov[4] = {po.x, po.y, po.z, po.w};
            float av[4] = {pa.x, pa.y, pa.z, pa.w};
            size_t base = (size_t)b * H_ + j;
            float4 cprev = *reinterpret_cast<const float4*>(&g_c[base]);
            float cp[4] = {cprev.x, cprev.y, cprev.z, cprev.w};
            float cnv[4], hnv[4];
            #pragma unroll
            for (int qq = 0; qq < 4; qq++) {
                float ff = 1.f / (1.f + expf(-fv[qq]));
                float ii = 1.f / (1.f + expf(-iv[qq]));
                float oo = 1.f / (1.f + expf(-ov[qq]));
                float cc = ii * tanhf(av[qq]) + ff * cp[qq];
                cnv[qq] = cc;
                hnv[qq] = oo * tanhf(cc);
            }
            float4 cn = {cnv[0], cnv[1], cnv[2], cnv[3]};
            float4 hn = {hnv[0], hnv[1], hnv[2], hnv[3]};
            *reinterpret_cast<float4*>(&g_c[base]) = cn;
            *reinterpret_cast<float4*>(&g_h[base]) = hn;
            *reinterpret_cast<float4*>(&g_Hbuf[(size_t)t * B_ * H_ + base]) = hn;
        }

        grid_barrier(2 * t + 2);
    }
}

// ---------------- launch ----------------
extern "C" void kernel_launch(void* const* d_in, const int* in_sizes, int n_in,
                              void* d_out, int out_size) {
    const float* x    = (const float*)d_in[0];
    const float* wfxw = (const float*)d_in[1];
    const float* wfxb = (const float*)d_in[2];
    const float* wixw = (const float*)d_in[3];
    const float* wixb = (const float*)d_in[4];
    const float* woxw = (const float*)d_in[5];
    const float* woxb = (const float*)d_in[6];
    const float* wcxw = (const float*)d_in[7];
    const float* wcxb = (const float*)d_in[8];
    const float* ufhw = (const float*)d_in[9];
    const float* uihw = (const float*)d_in[10];
    const float* uohw = (const float*)d_in[11];
    const float* uchw = (const float*)d_in[12];
    const float* fcow = (const float*)d_in[13];
    const float* fcob = (const float*)d_in[14];
    float* out = (float*)d_out;

    // launch order: recurrence must be the 4th kernel (ncu capture slot)
    build_W<<<(Fdim * N4 + 255) / 256, 256>>>(wfxw, wixw, woxw, wcxw);      // 1
    build_U_init<<<(H_ * N4 + 255) / 256, 256>>>(ufhw, uihw, uohw, uchw,
                                                 wfxb, wixb, woxb, wcxb);   // 2
    {   // input projections: G = x @ Wcat + bias                           // 3
        dim3 grid(N4 / 128, (T_ * B_) / 128);
        gemm_in<<<grid, 256>>>(x);
    }
    recurrence<<<NCTA, 256>>>();                                            // 4
    {   // output projection: out = Hbuf @ fco_w + fco_b                    // 5
        dim3 grid((FO + 127) / 128, (T_ * B_) / 128);
        gemm_out<<<grid, 256>>>(fcow, fcob, out);
    }
}